// round 12
// baseline (speedup 1.0000x reference)
#include <cuda_runtime.h>
#include <cuda_bf16.h>
#include <cuda_fp16.h>
#include <cstdint>

#define N_NODES 100000
#define N_EDGES 1600000
#define IN_CH   500
#define F1      64
#define H1      8
#define H2      8
#define F2      24
#define NEG_SLOPE 0.2f

#define KPAD    512
#define KC      32
#define NCHUNK  16
#define ASTR    40

#define SZ_A    (128 * ASTR * 2)
#define SZ_B    (64 * ASTR * 2)
#define OFF_AHI 0
#define OFF_ALO (2 * SZ_A)
#define OFF_BHI (4 * SZ_A)
#define OFF_BLO (4 * SZ_A + 2 * SZ_B)
#define SM_TOTAL (4 * SZ_A + 4 * SZ_B)

#define NB_SCAN ((N_NODES + 255) / 256)   // 391
#define XW2S    32                         // padded fp16 row stride for xw2

// ---------------- scratch -----------------------------------------------
__device__ __half g_xw1h[N_NODES * F1];
__device__ float g_h1  [N_NODES * F1];
__device__ float g_al1s[N_NODES * H1];
__device__ float g_al1d[N_NODES * H1];
__device__ __half g_xw2h[N_NODES * XW2S];
__device__ float g_al2s[N_NODES * H2];
__device__ float g_al2d[N_NODES * H2];
__device__ int   g_is64;
__device__ __nv_bfloat16 g_wt_hi[F1 * KPAD];
__device__ __nv_bfloat16 g_wt_lo[F1 * KPAD];
// CSR
__device__ int g_cnt   [N_NODES];
__device__ int g_rowptr[N_NODES + 1];
__device__ int g_woff  [N_NODES];
__device__ int g_esrc  [N_EDGES];
__device__ int g_edst  [N_EDGES];
__device__ int g_bsum  [NB_SCAN];
__device__ int g_bpre  [NB_SCAN];
// per-(edge,head) softmax weights (reused by both layers)
__device__ float g_ew  [N_EDGES * 8];

// ---------------- helpers ------------------------------------------------
__device__ __forceinline__ uint32_t smem_u32(const void* p) {
    uint32_t a;
    asm("{ .reg .u64 t; cvta.to.shared.u64 t, %1; cvt.u32.u64 %0, t; }"
        : "=r"(a) : "l"(p));
    return a;
}
__device__ __forceinline__ float leaky(float v) {
    return v > 0.f ? v : NEG_SLOPE * v;
}
__device__ __forceinline__ int edge_idx(const void* ei, int pos, int is64) {
    if (is64) return (int)((const long long*)ei)[pos];
    return ((const int*)ei)[pos];
}
__device__ __forceinline__ void cp16(uint32_t dst, const void* src) {
    asm volatile("cp.async.ca.shared.global [%0], [%1], 16;"
                 :: "r"(dst), "l"(src) : "memory");
}
__device__ __forceinline__ float4 ld_xw1h(size_t idx) {
    uint2 u = *(const uint2*)&g_xw1h[idx];
    __half2 a = *reinterpret_cast<__half2*>(&u.x);
    __half2 b = *reinterpret_cast<__half2*>(&u.y);
    float2 fa = __half22float2(a), fb = __half22float2(b);
    return make_float4(fa.x, fa.y, fb.x, fb.y);
}

#define LDMX4(r, addr) \
    asm volatile("ldmatrix.sync.aligned.m8n8.x4.shared.b16 {%0,%1,%2,%3}, [%4];" \
        : "=r"((r)[0]), "=r"((r)[1]), "=r"((r)[2]), "=r"((r)[3]) : "r"(addr))

#define MMA_BF16(d, a, b0v, b1v) \
    asm volatile("mma.sync.aligned.m16n8k16.row.col.f32.bf16.bf16.f32 " \
        "{%0,%1,%2,%3}, {%4,%5,%6,%7}, {%8,%9}, {%0,%1,%2,%3};" \
        : "+f"((d)[0]), "+f"((d)[1]), "+f"((d)[2]), "+f"((d)[3]) \
        : "r"((a)[0]), "r"((a)[1]), "r"((a)[2]), "r"((a)[3]), \
          "r"(b0v), "r"(b1v))

// ---------------- detect dtype + zero counts (merged) ---------------------
__global__ void detect_zcnt_kernel(const unsigned int* __restrict__ ei) {
    int i = blockIdx.x * blockDim.x + threadIdx.x;
    if (i < N_NODES) g_cnt[i] = 0;
    if (i == 0) {
        int all0 = 1;
        for (int j = 0; j < 64; j++)
            if (ei[2 * j + 1] != 0u) { all0 = 0; break; }
        g_is64 = all0;
    }
}

// ---------------- CSR build ----------------------------------------------
__global__ void hist_kernel(const void* __restrict__ ei) {
    int e = blockIdx.x * blockDim.x + threadIdx.x;
    if (e >= N_EDGES) return;
    int dst = edge_idx(ei, N_EDGES + e, g_is64);
    atomicAdd(&g_cnt[dst], 1);
}
__global__ void blocksum_kernel() {
    __shared__ int sred[256];
    int i = blockIdx.x * 256 + threadIdx.x;
    int v = (i < N_NODES) ? g_cnt[i] : 0;
    sred[threadIdx.x] = v;
    __syncthreads();
#pragma unroll
    for (int off = 128; off > 0; off >>= 1) {
        if (threadIdx.x < off) sred[threadIdx.x] += sred[threadIdx.x + off];
        __syncthreads();
    }
    if (threadIdx.x == 0) g_bsum[blockIdx.x] = sred[0];
}
__global__ void scan_bsum_kernel() {
    __shared__ int s[512];
    int t = threadIdx.x;
    s[t] = (t < NB_SCAN) ? g_bsum[t] : 0;
    __syncthreads();
#pragma unroll
    for (int off = 1; off < 512; off <<= 1) {
        int v = 0;
        if (t >= off) v = s[t - off];
        __syncthreads();
        s[t] += v;
        __syncthreads();
    }
    if (t < NB_SCAN) g_bpre[t] = (t == 0) ? 0 : s[t - 1];
    if (t == 0) g_rowptr[N_NODES] = N_EDGES;
}
__global__ void rowptr_kernel() {
    __shared__ int s[256];
    int b = blockIdx.x;
    int i = b * 256 + threadIdx.x;
    int t = threadIdx.x;
    int v = (i < N_NODES) ? g_cnt[i] : 0;
    s[t] = v;
    __syncthreads();
#pragma unroll
    for (int off = 1; off < 256; off <<= 1) {
        int u = 0;
        if (t >= off) u = s[t - off];
        __syncthreads();
        s[t] += u;
        __syncthreads();
    }
    if (i < N_NODES) {
        int excl = g_bpre[b] + s[t] - v;
        g_rowptr[i] = excl;
        g_woff[i] = excl;
    }
}
__global__ void scatter_kernel(const void* __restrict__ ei) {
    int e = blockIdx.x * blockDim.x + threadIdx.x;
    if (e >= N_EDGES) return;
    int is64 = g_is64;
    int src = edge_idx(ei, e, is64);
    int dst = edge_idx(ei, N_EDGES + e, is64);
    int pos = atomicAdd(&g_woff[dst], 1);
    g_esrc[pos] = src;
    g_edst[pos] = dst;
}

// ---------------- W1 transpose + bf16 split ------------------------------
__global__ void prep_w_kernel(const float* __restrict__ W) {
    int i = blockIdx.x * blockDim.x + threadIdx.x;
    if (i >= F1 * KPAD) return;
    int n = i >> 9, k = i & 511;
    float v = (k < IN_CH) ? W[k * F1 + n] : 0.f;
    __nv_bfloat16 h = __float2bfloat16(v);
    float lo = v - __bfloat162float(h);
    g_wt_hi[i] = h;
    g_wt_lo[i] = __float2bfloat16(lo);
}

// ---------------- gemm1: pipelined mma.sync bf16 3x-split ----------------
__global__ void __launch_bounds__(256) gemm1_mma(
        const float* __restrict__ x,
        const float* __restrict__ a1s,
        const float* __restrict__ a1d) {
    extern __shared__ char smem[];
    const uint32_t sb = smem_u32(smem);

    const int tid = threadIdx.x;
    const int lane = tid & 31, w = tid >> 5;
    const int wm = w >> 1, wn = w & 1;
    const int m0 = blockIdx.x * 128;

    float acc[2][4][4];
#pragma unroll
    for (int i = 0; i < 2; i++)
#pragma unroll
        for (int j = 0; j < 4; j++)
#pragma unroll
            for (int q = 0; q < 4; q++) acc[i][j][q] = 0.f;

    int arow[4], ak[4];
#pragma unroll
    for (int p = 0; p < 4; p++) {
        int idx = p * 256 + tid;
        arow[p] = idx >> 3;
        ak[p] = (idx & 7) * 4;
    }
    const int brow = tid >> 2;
    const int bke  = (tid & 3) * 8;

    float4 av[4];

    {
        const int k0 = 0;
        cp16(sb + OFF_BHI + (uint32_t)(brow * ASTR + bke) * 2,
             &g_wt_hi[brow * KPAD + k0 + bke]);
        cp16(sb + OFF_BLO + (uint32_t)(brow * ASTR + bke) * 2,
             &g_wt_lo[brow * KPAD + k0 + bke]);
        asm volatile("cp.async.commit_group;" ::: "memory");
#pragma unroll
        for (int p = 0; p < 4; p++) {
            int rg = m0 + arow[p], kg = k0 + ak[p];
            av[p] = make_float4(0.f, 0.f, 0.f, 0.f);
            if (rg < N_NODES && kg < IN_CH)
                av[p] = *(const float4*)&x[(size_t)rg * IN_CH + kg];
        }
#pragma unroll
        for (int p = 0; p < 4; p++) {
            float4 v = av[p];
            __nv_bfloat16 h0 = __float2bfloat16(v.x), h1 = __float2bfloat16(v.y),
                          h2 = __float2bfloat16(v.z), h3 = __float2bfloat16(v.w);
            __nv_bfloat16 l0 = __float2bfloat16(v.x - __bfloat162float(h0));
            __nv_bfloat16 l1 = __float2bfloat16(v.y - __bfloat162float(h1));
            __nv_bfloat16 l2 = __float2bfloat16(v.z - __bfloat162float(h2));
            __nv_bfloat16 l3 = __float2bfloat16(v.w - __bfloat162float(h3));
            uint32_t hi01 = ((uint32_t)__bfloat16_as_ushort(h1) << 16) | __bfloat16_as_ushort(h0);
            uint32_t hi23 = ((uint32_t)__bfloat16_as_ushort(h3) << 16) | __bfloat16_as_ushort(h2);
            uint32_t lo01 = ((uint32_t)__bfloat16_as_ushort(l1) << 16) | __bfloat16_as_ushort(l0);
            uint32_t lo23 = ((uint32_t)__bfloat16_as_ushort(l3) << 16) | __bfloat16_as_ushort(l2);
            uint32_t off = (uint32_t)(arow[p] * ASTR + ak[p]) * 2;
            asm volatile("st.shared.v2.b32 [%0], {%1,%2};" :: "r"(sb + OFF_AHI + off), "r"(hi01), "r"(hi23) : "memory");
            asm volatile("st.shared.v2.b32 [%0], {%1,%2};" :: "r"(sb + OFF_ALO + off), "r"(lo01), "r"(lo23) : "memory");
        }
        asm volatile("cp.async.wait_group 0;" ::: "memory");
        __syncthreads();
    }

    for (int ch = 0; ch < NCHUNK; ch++) {
        const int pb = ch & 1, nb = pb ^ 1;
        const bool more = (ch + 1) < NCHUNK;

        if (more) {
            const int k0 = (ch + 1) * KC;
            cp16(sb + OFF_BHI + nb * SZ_B + (uint32_t)(brow * ASTR + bke) * 2,
                 &g_wt_hi[brow * KPAD + k0 + bke]);
            cp16(sb + OFF_BLO + nb * SZ_B + (uint32_t)(brow * ASTR + bke) * 2,
                 &g_wt_lo[brow * KPAD + k0 + bke]);
            asm volatile("cp.async.commit_group;" ::: "memory");
#pragma unroll
            for (int p = 0; p < 4; p++) {
                int rg = m0 + arow[p], kg = k0 + ak[p];
                av[p] = make_float4(0.f, 0.f, 0.f, 0.f);
                if (rg < N_NODES && kg < IN_CH)
                    av[p] = *(const float4*)&x[(size_t)rg * IN_CH + kg];
            }
        }

        const uint32_t aHi = sb + OFF_AHI + pb * SZ_A;
        const uint32_t aLo = sb + OFF_ALO + pb * SZ_A;
        const uint32_t bHi = sb + OFF_BHI + pb * SZ_B;
        const uint32_t bLo = sb + OFF_BLO + pb * SZ_B;
#pragma unroll
        for (int ks = 0; ks < KC; ks += 16) {
            uint32_t ra_hi[2][4], ra_lo[2][4], rb_hi[2][4], rb_lo[2][4];
#pragma unroll
            for (int mt = 0; mt < 2; mt++) {
                uint32_t roff = (uint32_t)((wm * 32 + mt * 16 + (lane & 15)) * (ASTR * 2))
                              + ks * 2 + (lane & 16);
                LDMX4(ra_hi[mt], aHi + roff);
                LDMX4(ra_lo[mt], aLo + roff);
            }
#pragma unroll
            for (int pr = 0; pr < 2; pr++) {
                uint32_t n = wn * 32 + pr * 16 + (lane & 7) + ((lane & 16) >> 1);
                uint32_t roff = n * (ASTR * 2) + ks * 2 + ((lane & 8) << 1);
                LDMX4(rb_hi[pr], bHi + roff);
                LDMX4(rb_lo[pr], bLo + roff);
            }
#pragma unroll
            for (int mt = 0; mt < 2; mt++)
#pragma unroll
                for (int nt = 0; nt < 4; nt++) {
                    int pr = nt >> 1, sbi = (nt & 1) * 2;
                    MMA_BF16(acc[mt][nt], ra_hi[mt], rb_hi[pr][sbi], rb_hi[pr][sbi + 1]);
                    MMA_BF16(acc[mt][nt], ra_lo[mt], rb_hi[pr][sbi], rb_hi[pr][sbi + 1]);
                    MMA_BF16(acc[mt][nt], ra_hi[mt], rb_lo[pr][sbi], rb_lo[pr][sbi + 1]);
                }
        }

        if (more) {
#pragma unroll
            for (int p = 0; p < 4; p++) {
                float4 v = av[p];
                __nv_bfloat16 h0 = __float2bfloat16(v.x), h1 = __float2bfloat16(v.y),
                              h2 = __float2bfloat16(v.z), h3 = __float2bfloat16(v.w);
                __nv_bfloat16 l0 = __float2bfloat16(v.x - __bfloat162float(h0));
                __nv_bfloat16 l1 = __float2bfloat16(v.y - __bfloat162float(h1));
                __nv_bfloat16 l2 = __float2bfloat16(v.z - __bfloat162float(h2));
                __nv_bfloat16 l3 = __float2bfloat16(v.w - __bfloat162float(h3));
                uint32_t hi01 = ((uint32_t)__bfloat16_as_ushort(h1) << 16) | __bfloat16_as_ushort(h0);
                uint32_t hi23 = ((uint32_t)__bfloat16_as_ushort(h3) << 16) | __bfloat16_as_ushort(h2);
                uint32_t lo01 = ((uint32_t)__bfloat16_as_ushort(l1) << 16) | __bfloat16_as_ushort(l0);
                uint32_t lo23 = ((uint32_t)__bfloat16_as_ushort(l3) << 16) | __bfloat16_as_ushort(l2);
                uint32_t off = nb * SZ_A + (uint32_t)(arow[p] * ASTR + ak[p]) * 2;
                asm volatile("st.shared.v2.b32 [%0], {%1,%2};" :: "r"(sb + OFF_AHI + off), "r"(hi01), "r"(hi23) : "memory");
                asm volatile("st.shared.v2.b32 [%0], {%1,%2};" :: "r"(sb + OFF_ALO + off), "r"(lo01), "r"(lo23) : "memory");
            }
            asm volatile("cp.async.wait_group 0;" ::: "memory");
            __syncthreads();
        }
    }

    const int t = lane & 3, g = lane >> 2;
    float as0[4], as1[4], ad0[4], ad1[4];
#pragma unroll
    for (int nt = 0; nt < 4; nt++) {
        int c = wn * 32 + nt * 8 + 2 * t;
        as0[nt] = __ldg(&a1s[c]);  as1[nt] = __ldg(&a1s[c + 1]);
        ad0[nt] = __ldg(&a1d[c]);  ad1[nt] = __ldg(&a1d[c + 1]);
    }
#pragma unroll
    for (int mt = 0; mt < 2; mt++) {
        int r0 = m0 + wm * 32 + mt * 16 + g;
        int r1 = r0 + 8;
#pragma unroll
        for (int nt = 0; nt < 4; nt++) {
            int c = wn * 32 + nt * 8 + 2 * t;
            if (r0 < N_NODES)
                *(__half2*)&g_xw1h[(size_t)r0 * F1 + c] =
                    __floats2half2_rn(acc[mt][nt][0], acc[mt][nt][1]);
            if (r1 < N_NODES)
                *(__half2*)&g_xw1h[(size_t)r1 * F1 + c] =
                    __floats2half2_rn(acc[mt][nt][2], acc[mt][nt][3]);
        }
#pragma unroll
        for (int rsel = 0; rsel < 2; rsel++) {
            int row = rsel ? r1 : r0;
#pragma unroll
            for (int nt = 0; nt < 4; nt++) {
                float ps = acc[mt][nt][2 * rsel] * as0[nt] + acc[mt][nt][2 * rsel + 1] * as1[nt];
                float pd = acc[mt][nt][2 * rsel] * ad0[nt] + acc[mt][nt][2 * rsel + 1] * ad1[nt];
                ps += __shfl_xor_sync(0xffffffffu, ps, 1);
                ps += __shfl_xor_sync(0xffffffffu, ps, 2);
                pd += __shfl_xor_sync(0xffffffffu, pd, 1);
                pd += __shfl_xor_sync(0xffffffffu, pd, 2);
                if (t == 0 && row < N_NODES) {
                    g_al1s[row * H1 + wn * 4 + nt] = ps;
                    g_al1d[row * H1 + wn * 4 + nt] = pd;
                }
            }
        }
    }
}

// ---------------- ew: per-(edge,head) softmax weights, edge-parallel -------
__global__ void __launch_bounds__(256) ew_kernel(const float* __restrict__ als,
                                                 const float* __restrict__ ald) {
    int id = blockIdx.x * 256 + threadIdx.x;   // exactly 8*N_EDGES
    int pos = id >> 3, h = id & 7;
    int s = g_esrc[pos];
    int d = g_edst[pos];
    g_ew[id] = __expf(leaky(als[s * 8 + h] + ald[d * 8 + h]));
}

// ---------------- agg1: CSR gather, weights precomputed (16 lanes/node) ---
__global__ void __launch_bounds__(256) agg1_kernel(const float* __restrict__ b1) {
    int gid = blockIdx.x * 256 + threadIdx.x;
    int n = gid >> 4;
    int q = threadIdx.x & 15;
    int hq = q >> 1;

    float exs = __expf(leaky(g_al1s[n * H1 + hq] + g_al1d[n * H1 + hq]));
    float sw = exs;
    float4 vs = ld_xw1h((size_t)n * F1 + q * 4);
    float4 a0 = make_float4(exs * vs.x, exs * vs.y, exs * vs.z, exs * vs.w);
    float4 a1 = make_float4(0.f, 0.f, 0.f, 0.f);
    float4 a2 = make_float4(0.f, 0.f, 0.f, 0.f);
    float4 a3 = make_float4(0.f, 0.f, 0.f, 0.f);

    int p = g_rowptr[n];
    int pe = g_rowptr[n + 1];
    for (; p + 3 < pe; p += 4) {
        int s0 = __ldg(&g_esrc[p]);
        int s1 = __ldg(&g_esrc[p + 1]);
        int s2 = __ldg(&g_esrc[p + 2]);
        int s3 = __ldg(&g_esrc[p + 3]);
        float w0 = __ldg(&g_ew[(p)     * 8 + hq]);
        float w1 = __ldg(&g_ew[(p + 1) * 8 + hq]);
        float w2 = __ldg(&g_ew[(p + 2) * 8 + hq]);
        float w3 = __ldg(&g_ew[(p + 3) * 8 + hq]);
        float4 v0 = ld_xw1h((size_t)s0 * F1 + q * 4);
        float4 v1 = ld_xw1h((size_t)s1 * F1 + q * 4);
        float4 v2 = ld_xw1h((size_t)s2 * F1 + q * 4);
        float4 v3 = ld_xw1h((size_t)s3 * F1 + q * 4);
        a0.x += w0 * v0.x; a0.y += w0 * v0.y; a0.z += w0 * v0.z; a0.w += w0 * v0.w;
        a1.x += w1 * v1.x; a1.y += w1 * v1.y; a1.z += w1 * v1.z; a1.w += w1 * v1.w;
        a2.x += w2 * v2.x; a2.y += w2 * v2.y; a2.z += w2 * v2.z; a2.w += w2 * v2.w;
        a3.x += w3 * v3.x; a3.y += w3 * v3.y; a3.z += w3 * v3.z; a3.w += w3 * v3.w;
        sw += (w0 + w1) + (w2 + w3);
    }
    for (; p < pe; p++) {
        int s0 = __ldg(&g_esrc[p]);
        float w0 = __ldg(&g_ew[p * 8 + hq]);
        float4 v0 = ld_xw1h((size_t)s0 * F1 + q * 4);
        a0.x += w0 * v0.x; a0.y += w0 * v0.y; a0.z += w0 * v0.z; a0.w += w0 * v0.w;
        sw += w0;
    }
    a0.x += a1.x + a2.x + a3.x;
    a0.y += a1.y + a2.y + a3.y;
    a0.z += a1.z + a2.z + a3.z;
    a0.w += a1.w + a2.w + a3.w;

    float inv = 1.f / (sw + 1e-16f);
    float4 bb = *(const float4*)&b1[q * 4];
    float v0 = a0.x * inv + bb.x;
    float v1 = a0.y * inv + bb.y;
    float v2 = a0.z * inv + bb.z;
    float v3 = a0.w * inv + bb.w;
    v0 = v0 > 0.f ? v0 : expm1f(v0);
    v1 = v1 > 0.f ? v1 : expm1f(v1);
    v2 = v2 > 0.f ? v2 : expm1f(v2);
    v3 = v3 > 0.f ? v3 : expm1f(v3);
    *(float4*)&g_h1[(size_t)n * F1 + q * 4] = make_float4(v0, v1, v2, v3);
}

// ---------------- gemm2 + layer-2 logits ----------------------------------
__global__ void gemm2_kernel(const float* __restrict__ W2,
                             const float* __restrict__ a2s,
                             const float* __restrict__ a2d) {
    __shared__ float w2s[64 * F2];
    __shared__ float hs[8][64];
    int tid = threadIdx.x, lane = tid & 31, w = tid >> 5;
    for (int i = tid; i < 64 * F2; i += 256) w2s[i] = W2[i];
    __syncthreads();

    int node = blockIdx.x * 8 + w;
    if (node >= N_NODES) return;

    hs[w][lane]      = g_h1[(size_t)node * F1 + lane];
    hs[w][lane + 32] = g_h1[(size_t)node * F1 + 32 + lane];
    __syncwarp();

    float acc = 0.f;
    if (lane < F2) {
#pragma unroll 8
        for (int k = 0; k < 64; k++) acc += hs[w][k] * w2s[k * F2 + lane];
        g_xw2h[(size_t)node * XW2S + lane] = __float2half_rn(acc);
    }
    float ps = (lane < F2) ? acc * a2s[lane] : 0.f;
    float pd = (lane < F2) ? acc * a2d[lane] : 0.f;
    float ps1 = __shfl_down_sync(0xffffffffu, ps, 1);
    float ps2 = __shfl_down_sync(0xffffffffu, ps, 2);
    float pd1 = __shfl_down_sync(0xffffffffu, pd, 1);
    float pd2 = __shfl_down_sync(0xffffffffu, pd, 2);
    if (lane < F2 && (lane % 3) == 0) {
        g_al2s[node * H2 + lane / 3] = ps + ps1 + ps2;
        g_al2d[node * H2 + lane / 3] = pd + pd1 + pd2;
    }
}

// ---------------- agg2: CSR gather, weights precomputed (1 warp/node) -----
__global__ void __launch_bounds__(256) agg2_kernel(const float* __restrict__ b2,
                                                   float* __restrict__ out) {
    int n = (blockIdx.x * 256 + threadIdx.x) >> 5;
    int lane = threadIdx.x & 31;
    int head = (lane < F2) ? (lane / 3) : 0;

    float exs = __expf(leaky(g_al2s[n * H2 + head] + g_al2d[n * H2 + head]));
    float sw = exs;
    float vself = (lane < F2) ? __half2float(g_xw2h[(size_t)n * XW2S + lane]) : 0.f;
    float acc0 = exs * vself;
    float acc1 = 0.f;

    int p = g_rowptr[n];
    int pe = g_rowptr[n + 1];
    for (; p + 1 < pe; p += 2) {
        int s0 = __ldg(&g_esrc[p]);
        int s1 = __ldg(&g_esrc[p + 1]);
        float w0 = __ldg(&g_ew[(p)     * 8 + head]);
        float w1 = __ldg(&g_ew[(p + 1) * 8 + head]);
        float v0 = (lane < F2) ? __half2float(g_xw2h[(size_t)s0 * XW2S + lane]) : 0.f;
        float v1 = (lane < F2) ? __half2float(g_xw2h[(size_t)s1 * XW2S + lane]) : 0.f;
        acc0 += w0 * v0;
        acc1 += w1 * v1;
        sw += w0 + w1;
    }
    if (p < pe) {
        int s0 = __ldg(&g_esrc[p]);
        float w0 = __ldg(&g_ew[p * 8 + head]);
        float v0 = (lane < F2) ? __half2float(g_xw2h[(size_t)s0 * XW2S + lane]) : 0.f;
        acc0 += w0 * v0;
        sw += w0;
    }
    acc0 += acc1;

    float val = acc0 * (1.f / (sw + 1e-16f));

    float s = 0.f;
#pragma unroll
    for (int h = 0; h < H2; h++)
        s += __shfl_sync(0xffffffffu, val, h * 3 + (lane & 3), 32);
    float logit = s * 0.125f + ((lane < 3) ? __ldg(&b2[lane]) : 0.f);

    float l0 = __shfl_sync(0xffffffffu, logit, 0, 32);
    float l1 = __shfl_sync(0xffffffffu, logit, 1, 32);
    float l2 = __shfl_sync(0xffffffffu, logit, 2, 32);
    if (lane < 3) {
        float m = fmaxf(l0, fmaxf(l1, l2));
        float e0 = __expf(l0 - m), e1 = __expf(l1 - m), e2 = __expf(l2 - m);
        float invs = 1.f / (e0 + e1 + e2);
        out[n * 3 + lane] = __expf(logit - m) * invs;
    }
}

// ---------------- launch ----------------------------------------------------
extern "C" void kernel_launch(void* const* d_in, const int* in_sizes, int n_in,
                              void* d_out, int out_size) {
    const float* x   = (const float*)d_in[0];
    const float* W1  = (const float*)d_in[1];
    const float* a1s = (const float*)d_in[2];
    const float* a1d = (const float*)d_in[3];
    const float* b1  = (const float*)d_in[4];
    const float* W2  = (const float*)d_in[5];
    const float* a2s = (const float*)d_in[6];
    const float* a2d = (const float*)d_in[7];
    const float* b2  = (const float*)d_in[8];
    const void*  ei  = (const void*)d_in[9];
    float* out = (float*)d_out;

    (void)in_sizes; (void)n_in; (void)out_size;

    static int init_done = 0;
    static cudaStream_t sB;
    static cudaEvent_t evRoot, evB;
    if (!init_done) {
        cudaFuncSetAttribute(gemm1_mma,
                             cudaFuncAttributeMaxDynamicSharedMemorySize,
                             SM_TOTAL);
        cudaStreamCreateWithFlags(&sB, cudaStreamNonBlocking);
        cudaEventCreateWithFlags(&evRoot, cudaEventDisableTiming);
        cudaEventCreateWithFlags(&evB, cudaEventDisableTiming);
        init_done = 1;
    }

    float* al1s_p; float* al1d_p; float* al2s_p; float* al2d_p;
    cudaGetSymbolAddress((void**)&al1s_p, g_al1s);
    cudaGetSymbolAddress((void**)&al1d_p, g_al1d);
    cudaGetSymbolAddress((void**)&al2s_p, g_al2s);
    cudaGetSymbolAddress((void**)&al2d_p, g_al2d);

    // root
    detect_zcnt_kernel<<<(N_NODES + 255) / 256, 256>>>((const unsigned int*)ei);
    cudaEventRecord(evRoot, 0);
    cudaStreamWaitEvent(sB, evRoot, 0);

    // branch B (CSR build) on secondary stream
    hist_kernel<<<(N_EDGES + 255) / 256, 256, 0, sB>>>(ei);
    blocksum_kernel<<<NB_SCAN, 256, 0, sB>>>();
    scan_bsum_kernel<<<1, 512, 0, sB>>>();
    rowptr_kernel<<<NB_SCAN, 256, 0, sB>>>();
    scatter_kernel<<<(N_EDGES + 255) / 256, 256, 0, sB>>>(ei);
    cudaEventRecord(evB, sB);

    // branch A (dense path) on main stream
    prep_w_kernel<<<(F1 * KPAD + 255) / 256, 256>>>(W1);
    gemm1_mma<<<(N_NODES + 127) / 128, 256, SM_TOTAL>>>(x, a1s, a1d);

    // join, then aggregation pipeline
    cudaStreamWaitEvent(0, evB, 0);
    ew_kernel<<<(N_EDGES * 8) / 256, 256>>>(al1s_p, al1d_p);
    agg1_kernel<<<(N_NODES * 16) / 256, 256>>>(b1);
    gemm2_kernel<<<N_NODES / 8, 256>>>(W2, a2s, a2d);
    ew_kernel<<<(N_EDGES * 8) / 256, 256>>>(al2s_p, al2d_p);
    agg2_kernel<<<(N_NODES * 32) / 256, 256>>>(b2, out);
}

// round 13
// speedup vs baseline: 1.1035x; 1.1035x over previous
#include <cuda_runtime.h>
#include <cuda_bf16.h>
#include <cuda_fp16.h>
#include <cstdint>

#define N_NODES 100000
#define N_EDGES 1600000
#define IN_CH   500
#define F1      64
#define H1      8
#define H2      8
#define F2      24
#define NEG_SLOPE 0.2f

#define KPAD    512
#define KC      32
#define NCHUNK  16
#define ASTR    40

#define SZ_A    (128 * ASTR * 2)
#define SZ_B    (64 * ASTR * 2)
#define OFF_AHI 0
#define OFF_ALO (2 * SZ_A)
#define OFF_BHI (4 * SZ_A)
#define OFF_BLO (4 * SZ_A + 2 * SZ_B)
#define SM_TOTAL (4 * SZ_A + 4 * SZ_B)

#define NB_SCAN ((N_NODES + 255) / 256)   // 391
#define XW2S    32                         // padded fp16 row stride for xw2

// ---------------- scratch -----------------------------------------------
__device__ __half g_xw1h[N_NODES * F1];
__device__ float g_h1  [N_NODES * F1];
__device__ float g_al1s[N_NODES * H1];
__device__ float g_al1d[N_NODES * H1];
__device__ __half g_xw2h[N_NODES * XW2S];
__device__ float g_al2s[N_NODES * H2];
__device__ float g_al2d[N_NODES * H2];
__device__ int   g_is64;
__device__ __nv_bfloat16 g_wt_hi[F1 * KPAD];
__device__ __nv_bfloat16 g_wt_lo[F1 * KPAD];
// CSR
__device__ int g_cnt   [N_NODES];
__device__ int g_rowptr[N_NODES + 1];
__device__ int g_woff  [N_NODES];
__device__ int g_esrc  [N_EDGES];
__device__ int g_bsum  [NB_SCAN];
__device__ int g_bpre  [NB_SCAN];

// ---------------- helpers ------------------------------------------------
__device__ __forceinline__ uint32_t smem_u32(const void* p) {
    uint32_t a;
    asm("{ .reg .u64 t; cvta.to.shared.u64 t, %1; cvt.u32.u64 %0, t; }"
        : "=r"(a) : "l"(p));
    return a;
}
__device__ __forceinline__ float leaky(float v) {
    return v > 0.f ? v : NEG_SLOPE * v;
}
__device__ __forceinline__ int edge_idx(const void* ei, int pos, int is64) {
    if (is64) return (int)((const long long*)ei)[pos];
    return ((const int*)ei)[pos];
}
__device__ __forceinline__ void cp16(uint32_t dst, const void* src) {
    asm volatile("cp.async.ca.shared.global [%0], [%1], 16;"
                 :: "r"(dst), "l"(src) : "memory");
}
__device__ __forceinline__ float4 ld_xw1h(size_t idx) {
    uint2 u = *(const uint2*)&g_xw1h[idx];
    __half2 a = *reinterpret_cast<__half2*>(&u.x);
    __half2 b = *reinterpret_cast<__half2*>(&u.y);
    float2 fa = __half22float2(a), fb = __half22float2(b);
    return make_float4(fa.x, fa.y, fb.x, fb.y);
}

#define LDMX4(r, addr) \
    asm volatile("ldmatrix.sync.aligned.m8n8.x4.shared.b16 {%0,%1,%2,%3}, [%4];" \
        : "=r"((r)[0]), "=r"((r)[1]), "=r"((r)[2]), "=r"((r)[3]) : "r"(addr))

#define MMA_BF16(d, a, b0v, b1v) \
    asm volatile("mma.sync.aligned.m16n8k16.row.col.f32.bf16.bf16.f32 " \
        "{%0,%1,%2,%3}, {%4,%5,%6,%7}, {%8,%9}, {%0,%1,%2,%3};" \
        : "+f"((d)[0]), "+f"((d)[1]), "+f"((d)[2]), "+f"((d)[3]) \
        : "r"((a)[0]), "r"((a)[1]), "r"((a)[2]), "r"((a)[3]), \
          "r"(b0v), "r"(b1v))

// ---------------- detect dtype + zero counts (merged) ---------------------
__global__ void detect_zcnt_kernel(const unsigned int* __restrict__ ei) {
    int i = blockIdx.x * blockDim.x + threadIdx.x;
    if (i < N_NODES) g_cnt[i] = 0;
    if (i == 0) {
        int all0 = 1;
        for (int j = 0; j < 64; j++)
            if (ei[2 * j + 1] != 0u) { all0 = 0; break; }
        g_is64 = all0;
    }
}

// ---------------- CSR build ----------------------------------------------
__global__ void hist_kernel(const void* __restrict__ ei) {
    int e = blockIdx.x * blockDim.x + threadIdx.x;
    if (e >= N_EDGES) return;
    int dst = edge_idx(ei, N_EDGES + e, g_is64);
    atomicAdd(&g_cnt[dst], 1);
}
__global__ void blocksum_kernel() {
    __shared__ int sred[256];
    int i = blockIdx.x * 256 + threadIdx.x;
    int v = (i < N_NODES) ? g_cnt[i] : 0;
    sred[threadIdx.x] = v;
    __syncthreads();
#pragma unroll
    for (int off = 128; off > 0; off >>= 1) {
        if (threadIdx.x < off) sred[threadIdx.x] += sred[threadIdx.x + off];
        __syncthreads();
    }
    if (threadIdx.x == 0) g_bsum[blockIdx.x] = sred[0];
}
__global__ void scan_bsum_kernel() {
    __shared__ int s[512];
    int t = threadIdx.x;
    s[t] = (t < NB_SCAN) ? g_bsum[t] : 0;
    __syncthreads();
#pragma unroll
    for (int off = 1; off < 512; off <<= 1) {
        int v = 0;
        if (t >= off) v = s[t - off];
        __syncthreads();
        s[t] += v;
        __syncthreads();
    }
    if (t < NB_SCAN) g_bpre[t] = (t == 0) ? 0 : s[t - 1];
    if (t == 0) g_rowptr[N_NODES] = N_EDGES;
}
__global__ void rowptr_kernel() {
    __shared__ int s[256];
    int b = blockIdx.x;
    int i = b * 256 + threadIdx.x;
    int t = threadIdx.x;
    int v = (i < N_NODES) ? g_cnt[i] : 0;
    s[t] = v;
    __syncthreads();
#pragma unroll
    for (int off = 1; off < 256; off <<= 1) {
        int u = 0;
        if (t >= off) u = s[t - off];
        __syncthreads();
        s[t] += u;
        __syncthreads();
    }
    if (i < N_NODES) {
        int excl = g_bpre[b] + s[t] - v;
        g_rowptr[i] = excl;
        g_woff[i] = excl;
    }
}
__global__ void scatter_kernel(const void* __restrict__ ei) {
    int e = blockIdx.x * blockDim.x + threadIdx.x;
    if (e >= N_EDGES) return;
    int is64 = g_is64;
    int src = edge_idx(ei, e, is64);
    int dst = edge_idx(ei, N_EDGES + e, is64);
    int pos = atomicAdd(&g_woff[dst], 1);
    g_esrc[pos] = src;
}

// ---------------- W1 transpose + bf16 split ------------------------------
__global__ void prep_w_kernel(const float* __restrict__ W) {
    int i = blockIdx.x * blockDim.x + threadIdx.x;
    if (i >= F1 * KPAD) return;
    int n = i >> 9, k = i & 511;
    float v = (k < IN_CH) ? W[k * F1 + n] : 0.f;
    __nv_bfloat16 h = __float2bfloat16(v);
    float lo = v - __bfloat162float(h);
    g_wt_hi[i] = h;
    g_wt_lo[i] = __float2bfloat16(lo);
}

// ---------------- gemm1: pipelined mma.sync bf16 3x-split ----------------
__global__ void __launch_bounds__(256) gemm1_mma(
        const float* __restrict__ x,
        const float* __restrict__ a1s,
        const float* __restrict__ a1d) {
    extern __shared__ char smem[];
    const uint32_t sb = smem_u32(smem);

    const int tid = threadIdx.x;
    const int lane = tid & 31, w = tid >> 5;
    const int wm = w >> 1, wn = w & 1;
    const int m0 = blockIdx.x * 128;

    float acc[2][4][4];
#pragma unroll
    for (int i = 0; i < 2; i++)
#pragma unroll
        for (int j = 0; j < 4; j++)
#pragma unroll
            for (int q = 0; q < 4; q++) acc[i][j][q] = 0.f;

    int arow[4], ak[4];
#pragma unroll
    for (int p = 0; p < 4; p++) {
        int idx = p * 256 + tid;
        arow[p] = idx >> 3;
        ak[p] = (idx & 7) * 4;
    }
    const int brow = tid >> 2;
    const int bke  = (tid & 3) * 8;

    float4 av[4];

    {
        const int k0 = 0;
        cp16(sb + OFF_BHI + (uint32_t)(brow * ASTR + bke) * 2,
             &g_wt_hi[brow * KPAD + k0 + bke]);
        cp16(sb + OFF_BLO + (uint32_t)(brow * ASTR + bke) * 2,
             &g_wt_lo[brow * KPAD + k0 + bke]);
        asm volatile("cp.async.commit_group;" ::: "memory");
#pragma unroll
        for (int p = 0; p < 4; p++) {
            int rg = m0 + arow[p], kg = k0 + ak[p];
            av[p] = make_float4(0.f, 0.f, 0.f, 0.f);
            if (rg < N_NODES && kg < IN_CH)
                av[p] = *(const float4*)&x[(size_t)rg * IN_CH + kg];
        }
#pragma unroll
        for (int p = 0; p < 4; p++) {
            float4 v = av[p];
            __nv_bfloat16 h0 = __float2bfloat16(v.x), h1 = __float2bfloat16(v.y),
                          h2 = __float2bfloat16(v.z), h3 = __float2bfloat16(v.w);
            __nv_bfloat16 l0 = __float2bfloat16(v.x - __bfloat162float(h0));
            __nv_bfloat16 l1 = __float2bfloat16(v.y - __bfloat162float(h1));
            __nv_bfloat16 l2 = __float2bfloat16(v.z - __bfloat162float(h2));
            __nv_bfloat16 l3 = __float2bfloat16(v.w - __bfloat162float(h3));
            uint32_t hi01 = ((uint32_t)__bfloat16_as_ushort(h1) << 16) | __bfloat16_as_ushort(h0);
            uint32_t hi23 = ((uint32_t)__bfloat16_as_ushort(h3) << 16) | __bfloat16_as_ushort(h2);
            uint32_t lo01 = ((uint32_t)__bfloat16_as_ushort(l1) << 16) | __bfloat16_as_ushort(l0);
            uint32_t lo23 = ((uint32_t)__bfloat16_as_ushort(l3) << 16) | __bfloat16_as_ushort(l2);
            uint32_t off = (uint32_t)(arow[p] * ASTR + ak[p]) * 2;
            asm volatile("st.shared.v2.b32 [%0], {%1,%2};" :: "r"(sb + OFF_AHI + off), "r"(hi01), "r"(hi23) : "memory");
            asm volatile("st.shared.v2.b32 [%0], {%1,%2};" :: "r"(sb + OFF_ALO + off), "r"(lo01), "r"(lo23) : "memory");
        }
        asm volatile("cp.async.wait_group 0;" ::: "memory");
        __syncthreads();
    }

    for (int ch = 0; ch < NCHUNK; ch++) {
        const int pb = ch & 1, nb = pb ^ 1;
        const bool more = (ch + 1) < NCHUNK;

        if (more) {
            const int k0 = (ch + 1) * KC;
            cp16(sb + OFF_BHI + nb * SZ_B + (uint32_t)(brow * ASTR + bke) * 2,
                 &g_wt_hi[brow * KPAD + k0 + bke]);
            cp16(sb + OFF_BLO + nb * SZ_B + (uint32_t)(brow * ASTR + bke) * 2,
                 &g_wt_lo[brow * KPAD + k0 + bke]);
            asm volatile("cp.async.commit_group;" ::: "memory");
#pragma unroll
            for (int p = 0; p < 4; p++) {
                int rg = m0 + arow[p], kg = k0 + ak[p];
                av[p] = make_float4(0.f, 0.f, 0.f, 0.f);
                if (rg < N_NODES && kg < IN_CH)
                    av[p] = *(const float4*)&x[(size_t)rg * IN_CH + kg];
            }
        }

        const uint32_t aHi = sb + OFF_AHI + pb * SZ_A;
        const uint32_t aLo = sb + OFF_ALO + pb * SZ_A;
        const uint32_t bHi = sb + OFF_BHI + pb * SZ_B;
        const uint32_t bLo = sb + OFF_BLO + pb * SZ_B;
#pragma unroll
        for (int ks = 0; ks < KC; ks += 16) {
            uint32_t ra_hi[2][4], ra_lo[2][4], rb_hi[2][4], rb_lo[2][4];
#pragma unroll
            for (int mt = 0; mt < 2; mt++) {
                uint32_t roff = (uint32_t)((wm * 32 + mt * 16 + (lane & 15)) * (ASTR * 2))
                              + ks * 2 + (lane & 16);
                LDMX4(ra_hi[mt], aHi + roff);
                LDMX4(ra_lo[mt], aLo + roff);
            }
#pragma unroll
            for (int pr = 0; pr < 2; pr++) {
                uint32_t n = wn * 32 + pr * 16 + (lane & 7) + ((lane & 16) >> 1);
                uint32_t roff = n * (ASTR * 2) + ks * 2 + ((lane & 8) << 1);
                LDMX4(rb_hi[pr], bHi + roff);
                LDMX4(rb_lo[pr], bLo + roff);
            }
#pragma unroll
            for (int mt = 0; mt < 2; mt++)
#pragma unroll
                for (int nt = 0; nt < 4; nt++) {
                    int pr = nt >> 1, sbi = (nt & 1) * 2;
                    MMA_BF16(acc[mt][nt], ra_hi[mt], rb_hi[pr][sbi], rb_hi[pr][sbi + 1]);
                    MMA_BF16(acc[mt][nt], ra_lo[mt], rb_hi[pr][sbi], rb_hi[pr][sbi + 1]);
                    MMA_BF16(acc[mt][nt], ra_hi[mt], rb_lo[pr][sbi], rb_lo[pr][sbi + 1]);
                }
        }

        if (more) {
#pragma unroll
            for (int p = 0; p < 4; p++) {
                float4 v = av[p];
                __nv_bfloat16 h0 = __float2bfloat16(v.x), h1 = __float2bfloat16(v.y),
                              h2 = __float2bfloat16(v.z), h3 = __float2bfloat16(v.w);
                __nv_bfloat16 l0 = __float2bfloat16(v.x - __bfloat162float(h0));
                __nv_bfloat16 l1 = __float2bfloat16(v.y - __bfloat162float(h1));
                __nv_bfloat16 l2 = __float2bfloat16(v.z - __bfloat162float(h2));
                __nv_bfloat16 l3 = __float2bfloat16(v.w - __bfloat162float(h3));
                uint32_t hi01 = ((uint32_t)__bfloat16_as_ushort(h1) << 16) | __bfloat16_as_ushort(h0);
                uint32_t hi23 = ((uint32_t)__bfloat16_as_ushort(h3) << 16) | __bfloat16_as_ushort(h2);
                uint32_t lo01 = ((uint32_t)__bfloat16_as_ushort(l1) << 16) | __bfloat16_as_ushort(l0);
                uint32_t lo23 = ((uint32_t)__bfloat16_as_ushort(l3) << 16) | __bfloat16_as_ushort(l2);
                uint32_t off = nb * SZ_A + (uint32_t)(arow[p] * ASTR + ak[p]) * 2;
                asm volatile("st.shared.v2.b32 [%0], {%1,%2};" :: "r"(sb + OFF_AHI + off), "r"(hi01), "r"(hi23) : "memory");
                asm volatile("st.shared.v2.b32 [%0], {%1,%2};" :: "r"(sb + OFF_ALO + off), "r"(lo01), "r"(lo23) : "memory");
            }
            asm volatile("cp.async.wait_group 0;" ::: "memory");
            __syncthreads();
        }
    }

    const int t = lane & 3, g = lane >> 2;
    float as0[4], as1[4], ad0[4], ad1[4];
#pragma unroll
    for (int nt = 0; nt < 4; nt++) {
        int c = wn * 32 + nt * 8 + 2 * t;
        as0[nt] = __ldg(&a1s[c]);  as1[nt] = __ldg(&a1s[c + 1]);
        ad0[nt] = __ldg(&a1d[c]);  ad1[nt] = __ldg(&a1d[c + 1]);
    }
#pragma unroll
    for (int mt = 0; mt < 2; mt++) {
        int r0 = m0 + wm * 32 + mt * 16 + g;
        int r1 = r0 + 8;
#pragma unroll
        for (int nt = 0; nt < 4; nt++) {
            int c = wn * 32 + nt * 8 + 2 * t;
            if (r0 < N_NODES)
                *(__half2*)&g_xw1h[(size_t)r0 * F1 + c] =
                    __floats2half2_rn(acc[mt][nt][0], acc[mt][nt][1]);
            if (r1 < N_NODES)
                *(__half2*)&g_xw1h[(size_t)r1 * F1 + c] =
                    __floats2half2_rn(acc[mt][nt][2], acc[mt][nt][3]);
        }
#pragma unroll
        for (int rsel = 0; rsel < 2; rsel++) {
            int row = rsel ? r1 : r0;
#pragma unroll
            for (int nt = 0; nt < 4; nt++) {
                float ps = acc[mt][nt][2 * rsel] * as0[nt] + acc[mt][nt][2 * rsel + 1] * as1[nt];
                float pd = acc[mt][nt][2 * rsel] * ad0[nt] + acc[mt][nt][2 * rsel + 1] * ad1[nt];
                ps += __shfl_xor_sync(0xffffffffu, ps, 1);
                ps += __shfl_xor_sync(0xffffffffu, ps, 2);
                pd += __shfl_xor_sync(0xffffffffu, pd, 1);
                pd += __shfl_xor_sync(0xffffffffu, pd, 2);
                if (t == 0 && row < N_NODES) {
                    g_al1s[row * H1 + wn * 4 + nt] = ps;
                    g_al1d[row * H1 + wn * 4 + nt] = pd;
                }
            }
        }
    }
}

// ---------------- agg1: warp per node, two 16-lane groups split edges -----
__global__ void __launch_bounds__(256) agg1_kernel(const float* __restrict__ b1) {
    int n = (blockIdx.x * 256 + threadIdx.x) >> 5;   // exactly N_NODES warps
    int lane = threadIdx.x & 31;
    int q = lane & 15;
    int base16 = lane & 16;
    int grp = base16 >> 4;           // 0 or 1
    int hsel = base16 + (q >> 1);

    float ald_q = 0.f, ex_self = 0.f;
    if (q < 8) {
        ald_q = g_al1d[n * H1 + q];
        if (grp == 0)
            ex_self = __expf(leaky(g_al1s[n * H1 + q] + ald_q));
    }
    float sex = ex_self;                                 // head-q partial (lanes q<8)
    float eh = __shfl_sync(0xffffffffu, ex_self, q >> 1, 32);  // from group 0
    float4 vs = ld_xw1h((size_t)n * F1 + q * 4);
    float4 acc = make_float4(0.f, 0.f, 0.f, 0.f);
    if (grp == 0) {
        acc.x = eh * vs.x; acc.y = eh * vs.y;
        acc.z = eh * vs.z; acc.w = eh * vs.w;
    }

    int p0 = g_rowptr[n];
    int pe = g_rowptr[n + 1];
    int deg = pe - p0;
    int niter = (deg + 1) >> 1;     // uniform across warp
    int p = p0 + grp;
    for (int i = 0; i < niter; i++, p += 2) {
        bool act = p < pe;
        int s0 = act ? __ldg(&g_esrc[p]) : n;
        float ex = 0.f;
        if (q < 8 && act)
            ex = __expf(leaky(g_al1s[s0 * H1 + q] + ald_q));
        float e = __shfl_sync(0xffffffffu, ex, hsel, 32);
        float4 v = ld_xw1h((size_t)s0 * F1 + q * 4);
        acc.x += e * v.x; acc.y += e * v.y;
        acc.z += e * v.z; acc.w += e * v.w;
        sex += ex;
    }

    // combine the two groups
    acc.x += __shfl_xor_sync(0xffffffffu, acc.x, 16, 32);
    acc.y += __shfl_xor_sync(0xffffffffu, acc.y, 16, 32);
    acc.z += __shfl_xor_sync(0xffffffffu, acc.z, 16, 32);
    acc.w += __shfl_xor_sync(0xffffffffu, acc.w, 16, 32);
    sex   += __shfl_xor_sync(0xffffffffu, sex, 16, 32);

    float inv = 1.f / (__shfl_sync(0xffffffffu, sex, hsel, 32) + 1e-16f);
    float4 bb = *(const float4*)&b1[q * 4];
    float v0 = acc.x * inv + bb.x;
    float v1 = acc.y * inv + bb.y;
    float v2 = acc.z * inv + bb.z;
    float v3 = acc.w * inv + bb.w;
    v0 = v0 > 0.f ? v0 : expm1f(v0);
    v1 = v1 > 0.f ? v1 : expm1f(v1);
    v2 = v2 > 0.f ? v2 : expm1f(v2);
    v3 = v3 > 0.f ? v3 : expm1f(v3);
    if (grp == 0)
        *(float4*)&g_h1[(size_t)n * F1 + q * 4] = make_float4(v0, v1, v2, v3);
    else
        *(float4*)&g_h1[(size_t)n * F1 + q * 4] = make_float4(v0, v1, v2, v3);
}

// ---------------- gemm2 + layer-2 logits ----------------------------------
__global__ void gemm2_kernel(const float* __restrict__ W2,
                             const float* __restrict__ a2s,
                             const float* __restrict__ a2d) {
    __shared__ float w2s[64 * F2];
    __shared__ float hs[8][64];
    int tid = threadIdx.x, lane = tid & 31, w = tid >> 5;
    for (int i = tid; i < 64 * F2; i += 256) w2s[i] = W2[i];
    __syncthreads();

    int node = blockIdx.x * 8 + w;
    if (node >= N_NODES) return;

    hs[w][lane]      = g_h1[(size_t)node * F1 + lane];
    hs[w][lane + 32] = g_h1[(size_t)node * F1 + 32 + lane];
    __syncwarp();

    float acc = 0.f;
    if (lane < F2) {
#pragma unroll 8
        for (int k = 0; k < 64; k++) acc += hs[w][k] * w2s[k * F2 + lane];
        g_xw2h[(size_t)node * XW2S + lane] = __float2half_rn(acc);
    }
    float ps = (lane < F2) ? acc * a2s[lane] : 0.f;
    float pd = (lane < F2) ? acc * a2d[lane] : 0.f;
    float ps1 = __shfl_down_sync(0xffffffffu, ps, 1);
    float ps2 = __shfl_down_sync(0xffffffffu, ps, 2);
    float pd1 = __shfl_down_sync(0xffffffffu, pd, 1);
    float pd2 = __shfl_down_sync(0xffffffffu, pd, 2);
    if (lane < F2 && (lane % 3) == 0) {
        g_al2s[node * H2 + lane / 3] = ps + ps1 + ps2;
        g_al2d[node * H2 + lane / 3] = pd + pd1 + pd2;
    }
}

// ---------------- agg2: CSR gather (fp16 values), 1 warp/node -------------
__global__ void __launch_bounds__(256) agg2_kernel(const float* __restrict__ b2,
                                                   float* __restrict__ out) {
    int n = (blockIdx.x * 256 + threadIdx.x) >> 5;
    int lane = threadIdx.x & 31;
    int chead = (lane < F2) ? (lane / 3) : 0;

    float ald = 0.f, ex_self = 0.f;
    if (lane < 8) {
        ald = g_al2d[n * H2 + lane];
        ex_self = __expf(leaky(g_al2s[n * H2 + lane] + ald));
    }
    float sex = ex_self;
    float eh = __shfl_sync(0xffffffffu, ex_self, chead, 32);
    float vself = (lane < F2) ? __half2float(g_xw2h[(size_t)n * XW2S + lane]) : 0.f;
    float acc0 = eh * vself;
    float acc1 = 0.f;

    int p = g_rowptr[n];
    int deg = g_rowptr[n + 1] - p;

    int i = 0;
    for (; i + 1 < deg; i += 2) {
        int s0 = __ldg(&g_esrc[p + i]);
        int s1 = __ldg(&g_esrc[p + i + 1]);
        float ex0 = 0.f, ex1 = 0.f;
        if (lane < 8) {
            ex0 = __expf(leaky(g_al2s[s0 * H2 + lane] + ald));
            ex1 = __expf(leaky(g_al2s[s1 * H2 + lane] + ald));
        }
        float v0 = (lane < F2) ? __half2float(g_xw2h[(size_t)s0 * XW2S + lane]) : 0.f;
        float v1 = (lane < F2) ? __half2float(g_xw2h[(size_t)s1 * XW2S + lane]) : 0.f;
        float e0 = __shfl_sync(0xffffffffu, ex0, chead, 32);
        float e1 = __shfl_sync(0xffffffffu, ex1, chead, 32);
        acc0 += e0 * v0;
        acc1 += e1 * v1;
        sex += ex0 + ex1;
    }
    if (i < deg) {
        int s0 = __ldg(&g_esrc[p + i]);
        float ex0 = 0.f;
        if (lane < 8)
            ex0 = __expf(leaky(g_al2s[s0 * H2 + lane] + ald));
        float e0 = __shfl_sync(0xffffffffu, ex0, chead, 32);
        float v0 = (lane < F2) ? __half2float(g_xw2h[(size_t)s0 * XW2S + lane]) : 0.f;
        acc0 += e0 * v0;
        sex += ex0;
    }
    acc0 += acc1;

    float inv = 1.f / (__shfl_sync(0xffffffffu, sex, chead, 32) + 1e-16f);
    float val = acc0 * inv;

    float s = 0.f;
#pragma unroll
    for (int h = 0; h < H2; h++)
        s += __shfl_sync(0xffffffffu, val, h * 3 + (lane & 3), 32);
    float logit = s * 0.125f + ((lane < 3) ? __ldg(&b2[lane]) : 0.f);

    float l0 = __shfl_sync(0xffffffffu, logit, 0, 32);
    float l1 = __shfl_sync(0xffffffffu, logit, 1, 32);
    float l2 = __shfl_sync(0xffffffffu, logit, 2, 32);
    if (lane < 3) {
        float m = fmaxf(l0, fmaxf(l1, l2));
        float e0 = __expf(l0 - m), e1 = __expf(l1 - m), e2 = __expf(l2 - m);
        float invs = 1.f / (e0 + e1 + e2);
        out[n * 3 + lane] = __expf(logit - m) * invs;
    }
}

// ---------------- launch ----------------------------------------------------
extern "C" void kernel_launch(void* const* d_in, const int* in_sizes, int n_in,
                              void* d_out, int out_size) {
    const float* x   = (const float*)d_in[0];
    const float* W1  = (const float*)d_in[1];
    const float* a1s = (const float*)d_in[2];
    const float* a1d = (const float*)d_in[3];
    const float* b1  = (const float*)d_in[4];
    const float* W2  = (const float*)d_in[5];
    const float* a2s = (const float*)d_in[6];
    const float* a2d = (const float*)d_in[7];
    const float* b2  = (const float*)d_in[8];
    const void*  ei  = (const void*)d_in[9];
    float* out = (float*)d_out;

    (void)in_sizes; (void)n_in; (void)out_size;

    static int init_done = 0;
    static cudaStream_t sB;
    static cudaEvent_t evRoot, evB;
    if (!init_done) {
        cudaFuncSetAttribute(gemm1_mma,
                             cudaFuncAttributeMaxDynamicSharedMemorySize,
                             SM_TOTAL);
        cudaStreamCreateWithFlags(&sB, cudaStreamNonBlocking);
        cudaEventCreateWithFlags(&evRoot, cudaEventDisableTiming);
        cudaEventCreateWithFlags(&evB, cudaEventDisableTiming);
        init_done = 1;
    }

    // root
    detect_zcnt_kernel<<<(N_NODES + 255) / 256, 256>>>((const unsigned int*)ei);
    cudaEventRecord(evRoot, 0);
    cudaStreamWaitEvent(sB, evRoot, 0);

    // branch B (CSR build) on secondary stream
    hist_kernel<<<(N_EDGES + 255) / 256, 256, 0, sB>>>(ei);
    blocksum_kernel<<<NB_SCAN, 256, 0, sB>>>();
    scan_bsum_kernel<<<1, 512, 0, sB>>>();
    rowptr_kernel<<<NB_SCAN, 256, 0, sB>>>();
    scatter_kernel<<<(N_EDGES + 255) / 256, 256, 0, sB>>>(ei);
    cudaEventRecord(evB, sB);

    // branch A (dense path) on main stream
    prep_w_kernel<<<(F1 * KPAD + 255) / 256, 256>>>(W1);
    gemm1_mma<<<(N_NODES + 127) / 128, 256, SM_TOTAL>>>(x, a1s, a1d);

    // join, then aggregation pipeline
    cudaStreamWaitEvent(0, evB, 0);
    agg1_kernel<<<(N_NODES * 32) / 256, 256>>>(b1);
    gemm2_kernel<<<N_NODES / 8, 256>>>(W2, a2s, a2d);
    agg2_kernel<<<(N_NODES * 32) / 256, 256>>>(b2, out);
}

// round 14
// speedup vs baseline: 1.2526x; 1.1351x over previous
#include <cuda_runtime.h>
#include <cuda_bf16.h>
#include <cuda_fp16.h>
#include <cstdint>

#define N_NODES 100000
#define N_EDGES 1600000
#define IN_CH   500
#define F1      64
#define H1      8
#define H2      8
#define F2      24
#define NEG_SLOPE 0.2f

#define KPAD    512
#define KC      32
#define NCHUNK  16
#define ASTR    40

#define SZ_A    (128 * ASTR * 2)
#define SZ_B    (64 * ASTR * 2)
#define OFF_AHI 0
#define OFF_ALO (2 * SZ_A)
#define OFF_BHI (4 * SZ_A)
#define OFF_BLO (4 * SZ_A + 2 * SZ_B)
#define SM_TOTAL (4 * SZ_A + 4 * SZ_B)

#define NB_SCAN ((N_NODES + 255) / 256)   // 391
#define XW2S    32                         // padded fp16 row stride for xw2

// ---------------- scratch -----------------------------------------------
__device__ __half g_xw1h[N_NODES * F1];
__device__ float g_al1s[N_NODES * H1];
__device__ float g_al1d[N_NODES * H1];
__device__ __half g_xw2h[N_NODES * XW2S];
__device__ float g_al2s[N_NODES * H2];
__device__ float g_al2d[N_NODES * H2];
__device__ int   g_is64;
__device__ __nv_bfloat16 g_wt_hi[F1 * KPAD];
__device__ __nv_bfloat16 g_wt_lo[F1 * KPAD];
// CSR
__device__ int g_cnt   [N_NODES];
__device__ int g_rowptr[N_NODES + 1];
__device__ int g_woff  [N_NODES];
__device__ int g_esrc  [N_EDGES];
__device__ int g_bsum  [NB_SCAN];
__device__ int g_bpre  [NB_SCAN];

// ---------------- helpers ------------------------------------------------
__device__ __forceinline__ uint32_t smem_u32(const void* p) {
    uint32_t a;
    asm("{ .reg .u64 t; cvta.to.shared.u64 t, %1; cvt.u32.u64 %0, t; }"
        : "=r"(a) : "l"(p));
    return a;
}
__device__ __forceinline__ float leaky(float v) {
    return v > 0.f ? v : NEG_SLOPE * v;
}
__device__ __forceinline__ int edge_idx(const void* ei, int pos, int is64) {
    if (is64) return (int)((const long long*)ei)[pos];
    return ((const int*)ei)[pos];
}
__device__ __forceinline__ void cp16(uint32_t dst, const void* src) {
    asm volatile("cp.async.ca.shared.global [%0], [%1], 16;"
                 :: "r"(dst), "l"(src) : "memory");
}
__device__ __forceinline__ float4 ld_xw1h(size_t idx) {
    uint2 u = *(const uint2*)&g_xw1h[idx];
    __half2 a = *reinterpret_cast<__half2*>(&u.x);
    __half2 b = *reinterpret_cast<__half2*>(&u.y);
    float2 fa = __half22float2(a), fb = __half22float2(b);
    return make_float4(fa.x, fa.y, fb.x, fb.y);
}

#define LDMX4(r, addr) \
    asm volatile("ldmatrix.sync.aligned.m8n8.x4.shared.b16 {%0,%1,%2,%3}, [%4];" \
        : "=r"((r)[0]), "=r"((r)[1]), "=r"((r)[2]), "=r"((r)[3]) : "r"(addr))

#define MMA_BF16(d, a, b0v, b1v) \
    asm volatile("mma.sync.aligned.m16n8k16.row.col.f32.bf16.bf16.f32 " \
        "{%0,%1,%2,%3}, {%4,%5,%6,%7}, {%8,%9}, {%0,%1,%2,%3};" \
        : "+f"((d)[0]), "+f"((d)[1]), "+f"((d)[2]), "+f"((d)[3]) \
        : "r"((a)[0]), "r"((a)[1]), "r"((a)[2]), "r"((a)[3]), \
          "r"(b0v), "r"(b1v))

// ---------------- detect dtype + zero counts (merged) ---------------------
__global__ void detect_zcnt_kernel(const unsigned int* __restrict__ ei) {
    int i = blockIdx.x * blockDim.x + threadIdx.x;
    if (i < N_NODES) g_cnt[i] = 0;
    if (i == 0) {
        int all0 = 1;
        for (int j = 0; j < 64; j++)
            if (ei[2 * j + 1] != 0u) { all0 = 0; break; }
        g_is64 = all0;
    }
}

// ---------------- CSR build ----------------------------------------------
__global__ void hist_kernel(const void* __restrict__ ei) {
    int e = blockIdx.x * blockDim.x + threadIdx.x;
    if (e >= N_EDGES) return;
    int dst = edge_idx(ei, N_EDGES + e, g_is64);
    atomicAdd(&g_cnt[dst], 1);
}
__global__ void blocksum_kernel() {
    __shared__ int sred[256];
    int i = blockIdx.x * 256 + threadIdx.x;
    int v = (i < N_NODES) ? g_cnt[i] : 0;
    sred[threadIdx.x] = v;
    __syncthreads();
#pragma unroll
    for (int off = 128; off > 0; off >>= 1) {
        if (threadIdx.x < off) sred[threadIdx.x] += sred[threadIdx.x + off];
        __syncthreads();
    }
    if (threadIdx.x == 0) g_bsum[blockIdx.x] = sred[0];
}
__global__ void scan_bsum_kernel() {
    __shared__ int s[512];
    int t = threadIdx.x;
    s[t] = (t < NB_SCAN) ? g_bsum[t] : 0;
    __syncthreads();
#pragma unroll
    for (int off = 1; off < 512; off <<= 1) {
        int v = 0;
        if (t >= off) v = s[t - off];
        __syncthreads();
        s[t] += v;
        __syncthreads();
    }
    if (t < NB_SCAN) g_bpre[t] = (t == 0) ? 0 : s[t - 1];
    if (t == 0) g_rowptr[N_NODES] = N_EDGES;
}
__global__ void rowptr_kernel() {
    __shared__ int s[256];
    int b = blockIdx.x;
    int i = b * 256 + threadIdx.x;
    int t = threadIdx.x;
    int v = (i < N_NODES) ? g_cnt[i] : 0;
    s[t] = v;
    __syncthreads();
#pragma unroll
    for (int off = 1; off < 256; off <<= 1) {
        int u = 0;
        if (t >= off) u = s[t - off];
        __syncthreads();
        s[t] += u;
        __syncthreads();
    }
    if (i < N_NODES) {
        int excl = g_bpre[b] + s[t] - v;
        g_rowptr[i] = excl;
        g_woff[i] = excl;
    }
}
__global__ void scatter_kernel(const void* __restrict__ ei) {
    int e = blockIdx.x * blockDim.x + threadIdx.x;
    if (e >= N_EDGES) return;
    int is64 = g_is64;
    int src = edge_idx(ei, e, is64);
    int dst = edge_idx(ei, N_EDGES + e, is64);
    int pos = atomicAdd(&g_woff[dst], 1);
    g_esrc[pos] = src;
}

// ---------------- W1 transpose + bf16 split ------------------------------
__global__ void prep_w_kernel(const float* __restrict__ W) {
    int i = blockIdx.x * blockDim.x + threadIdx.x;
    if (i >= F1 * KPAD) return;
    int n = i >> 9, k = i & 511;
    float v = (k < IN_CH) ? W[k * F1 + n] : 0.f;
    __nv_bfloat16 h = __float2bfloat16(v);
    float lo = v - __bfloat162float(h);
    g_wt_hi[i] = h;
    g_wt_lo[i] = __float2bfloat16(lo);
}

// ---------------- gemm1: pipelined mma.sync bf16 3x-split ----------------
__global__ void __launch_bounds__(256) gemm1_mma(
        const float* __restrict__ x,
        const float* __restrict__ a1s,
        const float* __restrict__ a1d) {
    extern __shared__ char smem[];
    const uint32_t sb = smem_u32(smem);

    const int tid = threadIdx.x;
    const int lane = tid & 31, w = tid >> 5;
    const int wm = w >> 1, wn = w & 1;
    const int m0 = blockIdx.x * 128;

    float acc[2][4][4];
#pragma unroll
    for (int i = 0; i < 2; i++)
#pragma unroll
        for (int j = 0; j < 4; j++)
#pragma unroll
            for (int q = 0; q < 4; q++) acc[i][j][q] = 0.f;

    int arow[4], ak[4];
#pragma unroll
    for (int p = 0; p < 4; p++) {
        int idx = p * 256 + tid;
        arow[p] = idx >> 3;
        ak[p] = (idx & 7) * 4;
    }
    const int brow = tid >> 2;
    const int bke  = (tid & 3) * 8;

    float4 av[4];

    {
        const int k0 = 0;
        cp16(sb + OFF_BHI + (uint32_t)(brow * ASTR + bke) * 2,
             &g_wt_hi[brow * KPAD + k0 + bke]);
        cp16(sb + OFF_BLO + (uint32_t)(brow * ASTR + bke) * 2,
             &g_wt_lo[brow * KPAD + k0 + bke]);
        asm volatile("cp.async.commit_group;" ::: "memory");
#pragma unroll
        for (int p = 0; p < 4; p++) {
            int rg = m0 + arow[p], kg = k0 + ak[p];
            av[p] = make_float4(0.f, 0.f, 0.f, 0.f);
            if (rg < N_NODES && kg < IN_CH)
                av[p] = *(const float4*)&x[(size_t)rg * IN_CH + kg];
        }
#pragma unroll
        for (int p = 0; p < 4; p++) {
            float4 v = av[p];
            __nv_bfloat16 h0 = __float2bfloat16(v.x), h1 = __float2bfloat16(v.y),
                          h2 = __float2bfloat16(v.z), h3 = __float2bfloat16(v.w);
            __nv_bfloat16 l0 = __float2bfloat16(v.x - __bfloat162float(h0));
            __nv_bfloat16 l1 = __float2bfloat16(v.y - __bfloat162float(h1));
            __nv_bfloat16 l2 = __float2bfloat16(v.z - __bfloat162float(h2));
            __nv_bfloat16 l3 = __float2bfloat16(v.w - __bfloat162float(h3));
            uint32_t hi01 = ((uint32_t)__bfloat16_as_ushort(h1) << 16) | __bfloat16_as_ushort(h0);
            uint32_t hi23 = ((uint32_t)__bfloat16_as_ushort(h3) << 16) | __bfloat16_as_ushort(h2);
            uint32_t lo01 = ((uint32_t)__bfloat16_as_ushort(l1) << 16) | __bfloat16_as_ushort(l0);
            uint32_t lo23 = ((uint32_t)__bfloat16_as_ushort(l3) << 16) | __bfloat16_as_ushort(l2);
            uint32_t off = (uint32_t)(arow[p] * ASTR + ak[p]) * 2;
            asm volatile("st.shared.v2.b32 [%0], {%1,%2};" :: "r"(sb + OFF_AHI + off), "r"(hi01), "r"(hi23) : "memory");
            asm volatile("st.shared.v2.b32 [%0], {%1,%2};" :: "r"(sb + OFF_ALO + off), "r"(lo01), "r"(lo23) : "memory");
        }
        asm volatile("cp.async.wait_group 0;" ::: "memory");
        __syncthreads();
    }

    for (int ch = 0; ch < NCHUNK; ch++) {
        const int pb = ch & 1, nb = pb ^ 1;
        const bool more = (ch + 1) < NCHUNK;

        if (more) {
            const int k0 = (ch + 1) * KC;
            cp16(sb + OFF_BHI + nb * SZ_B + (uint32_t)(brow * ASTR + bke) * 2,
                 &g_wt_hi[brow * KPAD + k0 + bke]);
            cp16(sb + OFF_BLO + nb * SZ_B + (uint32_t)(brow * ASTR + bke) * 2,
                 &g_wt_lo[brow * KPAD + k0 + bke]);
            asm volatile("cp.async.commit_group;" ::: "memory");
#pragma unroll
            for (int p = 0; p < 4; p++) {
                int rg = m0 + arow[p], kg = k0 + ak[p];
                av[p] = make_float4(0.f, 0.f, 0.f, 0.f);
                if (rg < N_NODES && kg < IN_CH)
                    av[p] = *(const float4*)&x[(size_t)rg * IN_CH + kg];
            }
        }

        const uint32_t aHi = sb + OFF_AHI + pb * SZ_A;
        const uint32_t aLo = sb + OFF_ALO + pb * SZ_A;
        const uint32_t bHi = sb + OFF_BHI + pb * SZ_B;
        const uint32_t bLo = sb + OFF_BLO + pb * SZ_B;
#pragma unroll
        for (int ks = 0; ks < KC; ks += 16) {
            uint32_t ra_hi[2][4], ra_lo[2][4], rb_hi[2][4], rb_lo[2][4];
#pragma unroll
            for (int mt = 0; mt < 2; mt++) {
                uint32_t roff = (uint32_t)((wm * 32 + mt * 16 + (lane & 15)) * (ASTR * 2))
                              + ks * 2 + (lane & 16);
                LDMX4(ra_hi[mt], aHi + roff);
                LDMX4(ra_lo[mt], aLo + roff);
            }
#pragma unroll
            for (int pr = 0; pr < 2; pr++) {
                uint32_t n = wn * 32 + pr * 16 + (lane & 7) + ((lane & 16) >> 1);
                uint32_t roff = n * (ASTR * 2) + ks * 2 + ((lane & 8) << 1);
                LDMX4(rb_hi[pr], bHi + roff);
                LDMX4(rb_lo[pr], bLo + roff);
            }
#pragma unroll
            for (int mt = 0; mt < 2; mt++)
#pragma unroll
                for (int nt = 0; nt < 4; nt++) {
                    int pr = nt >> 1, sbi = (nt & 1) * 2;
                    MMA_BF16(acc[mt][nt], ra_hi[mt], rb_hi[pr][sbi], rb_hi[pr][sbi + 1]);
                    MMA_BF16(acc[mt][nt], ra_lo[mt], rb_hi[pr][sbi], rb_hi[pr][sbi + 1]);
                    MMA_BF16(acc[mt][nt], ra_hi[mt], rb_lo[pr][sbi], rb_lo[pr][sbi + 1]);
                }
        }

        if (more) {
#pragma unroll
            for (int p = 0; p < 4; p++) {
                float4 v = av[p];
                __nv_bfloat16 h0 = __float2bfloat16(v.x), h1 = __float2bfloat16(v.y),
                              h2 = __float2bfloat16(v.z), h3 = __float2bfloat16(v.w);
                __nv_bfloat16 l0 = __float2bfloat16(v.x - __bfloat162float(h0));
                __nv_bfloat16 l1 = __float2bfloat16(v.y - __bfloat162float(h1));
                __nv_bfloat16 l2 = __float2bfloat16(v.z - __bfloat162float(h2));
                __nv_bfloat16 l3 = __float2bfloat16(v.w - __bfloat162float(h3));
                uint32_t hi01 = ((uint32_t)__bfloat16_as_ushort(h1) << 16) | __bfloat16_as_ushort(h0);
                uint32_t hi23 = ((uint32_t)__bfloat16_as_ushort(h3) << 16) | __bfloat16_as_ushort(h2);
                uint32_t lo01 = ((uint32_t)__bfloat16_as_ushort(l1) << 16) | __bfloat16_as_ushort(l0);
                uint32_t lo23 = ((uint32_t)__bfloat16_as_ushort(l3) << 16) | __bfloat16_as_ushort(l2);
                uint32_t off = nb * SZ_A + (uint32_t)(arow[p] * ASTR + ak[p]) * 2;
                asm volatile("st.shared.v2.b32 [%0], {%1,%2};" :: "r"(sb + OFF_AHI + off), "r"(hi01), "r"(hi23) : "memory");
                asm volatile("st.shared.v2.b32 [%0], {%1,%2};" :: "r"(sb + OFF_ALO + off), "r"(lo01), "r"(lo23) : "memory");
            }
            asm volatile("cp.async.wait_group 0;" ::: "memory");
            __syncthreads();
        }
    }

    const int t = lane & 3, g = lane >> 2;
    float as0[4], as1[4], ad0[4], ad1[4];
#pragma unroll
    for (int nt = 0; nt < 4; nt++) {
        int c = wn * 32 + nt * 8 + 2 * t;
        as0[nt] = __ldg(&a1s[c]);  as1[nt] = __ldg(&a1s[c + 1]);
        ad0[nt] = __ldg(&a1d[c]);  ad1[nt] = __ldg(&a1d[c + 1]);
    }
#pragma unroll
    for (int mt = 0; mt < 2; mt++) {
        int r0 = m0 + wm * 32 + mt * 16 + g;
        int r1 = r0 + 8;
#pragma unroll
        for (int nt = 0; nt < 4; nt++) {
            int c = wn * 32 + nt * 8 + 2 * t;
            if (r0 < N_NODES)
                *(__half2*)&g_xw1h[(size_t)r0 * F1 + c] =
                    __floats2half2_rn(acc[mt][nt][0], acc[mt][nt][1]);
            if (r1 < N_NODES)
                *(__half2*)&g_xw1h[(size_t)r1 * F1 + c] =
                    __floats2half2_rn(acc[mt][nt][2], acc[mt][nt][3]);
        }
#pragma unroll
        for (int rsel = 0; rsel < 2; rsel++) {
            int row = rsel ? r1 : r0;
#pragma unroll
            for (int nt = 0; nt < 4; nt++) {
                float ps = acc[mt][nt][2 * rsel] * as0[nt] + acc[mt][nt][2 * rsel + 1] * as1[nt];
                float pd = acc[mt][nt][2 * rsel] * ad0[nt] + acc[mt][nt][2 * rsel + 1] * ad1[nt];
                ps += __shfl_xor_sync(0xffffffffu, ps, 1);
                ps += __shfl_xor_sync(0xffffffffu, ps, 2);
                pd += __shfl_xor_sync(0xffffffffu, pd, 1);
                pd += __shfl_xor_sync(0xffffffffu, pd, 2);
                if (t == 0 && row < N_NODES) {
                    g_al1s[row * H1 + wn * 4 + nt] = ps;
                    g_al1d[row * H1 + wn * 4 + nt] = pd;
                }
            }
        }
    }
}

// ---------------- agg1 fused with gemm2 + layer-2 logits -------------------
// 16 lanes per node (2 nodes/warp, 16 groups/block), R10 gather loop,
// then h1 -> smem -> 64x24 GEMM -> xw2h + al2s/al2d, no global h1.
__global__ void __launch_bounds__(256) agg1_fused(
        const float* __restrict__ b1,
        const float* __restrict__ W2,
        const float* __restrict__ a2s,
        const float* __restrict__ a2d) {
    __shared__ float w2s[64 * F2];         // 6 KB
    __shared__ float hs[16][F1];           // 4 KB
    __shared__ float xs[16][F2];           // 1.5 KB

    int tid = threadIdx.x;
    for (int i = tid; i < 64 * F2; i += 256) w2s[i] = W2[i];
    __syncthreads();

    int gid = blockIdx.x * 256 + tid;
    int n = gid >> 4;
    int q = tid & 15;
    int gb = tid >> 4;              // group index in block (0..15)
    int base16 = tid & 16;
    int hsel = base16 + (q >> 1);
    int hq = q >> 1;

    // ---- layer-1 aggregation (identical structure to the 303.1 version) ----
    float ald_q = 0.f, ex_self = 0.f;
    if (q < 8) {
        ald_q = g_al1d[n * H1 + q];
        ex_self = __expf(leaky(g_al1s[n * H1 + q] + ald_q));
    }
    float sex = ex_self;
    float eh = __shfl_sync(0xffffffffu, ex_self, hsel, 32);
    float4 vs = ld_xw1h((size_t)n * F1 + q * 4);
    float4 acc0 = make_float4(eh * vs.x, eh * vs.y, eh * vs.z, eh * vs.w);
    float4 acc1 = make_float4(0.f, 0.f, 0.f, 0.f);

    int p = g_rowptr[n];
    int deg = g_rowptr[n + 1] - p;
    int mdeg = max(deg, __shfl_xor_sync(0xffffffffu, deg, 16, 32));

    int i = 0;
    for (; i + 1 < mdeg; i += 2) {
        bool a0 = i < deg, a1 = (i + 1) < deg;
        int s0 = a0 ? __ldg(&g_esrc[p + i]) : n;
        int s1 = a1 ? __ldg(&g_esrc[p + i + 1]) : n;
        float ex0 = 0.f, ex1 = 0.f;
        if (q < 8) {
            if (a0) ex0 = __expf(leaky(g_al1s[s0 * H1 + q] + ald_q));
            if (a1) ex1 = __expf(leaky(g_al1s[s1 * H1 + q] + ald_q));
        }
        float4 v0 = ld_xw1h((size_t)s0 * F1 + q * 4);
        float4 v1 = ld_xw1h((size_t)s1 * F1 + q * 4);
        float e0 = __shfl_sync(0xffffffffu, ex0, hsel, 32);
        float e1 = __shfl_sync(0xffffffffu, ex1, hsel, 32);
        acc0.x += e0 * v0.x; acc0.y += e0 * v0.y;
        acc0.z += e0 * v0.z; acc0.w += e0 * v0.w;
        acc1.x += e1 * v1.x; acc1.y += e1 * v1.y;
        acc1.z += e1 * v1.z; acc1.w += e1 * v1.w;
        sex += ex0 + ex1;
    }
    if (i < mdeg) {
        bool a0 = i < deg;
        int s0 = a0 ? __ldg(&g_esrc[p + i]) : n;
        float ex0 = 0.f;
        if (q < 8 && a0)
            ex0 = __expf(leaky(g_al1s[s0 * H1 + q] + ald_q));
        float e0 = __shfl_sync(0xffffffffu, ex0, hsel, 32);
        float4 v0 = ld_xw1h((size_t)s0 * F1 + q * 4);
        acc0.x += e0 * v0.x; acc0.y += e0 * v0.y;
        acc0.z += e0 * v0.z; acc0.w += e0 * v0.w;
        sex += ex0;
    }
    acc0.x += acc1.x; acc0.y += acc1.y;
    acc0.z += acc1.z; acc0.w += acc1.w;

    float inv = 1.f / (__shfl_sync(0xffffffffu, sex, hsel, 32) + 1e-16f);
    float4 bb = *(const float4*)&b1[q * 4];
    float v0 = acc0.x * inv + bb.x;
    float v1 = acc0.y * inv + bb.y;
    float v2 = acc0.z * inv + bb.z;
    float v3 = acc0.w * inv + bb.w;
    v0 = v0 > 0.f ? v0 : expm1f(v0);
    v1 = v1 > 0.f ? v1 : expm1f(v1);
    v2 = v2 > 0.f ? v2 : expm1f(v2);
    v3 = v3 > 0.f ? v3 : expm1f(v3);

    // ---- h1 -> smem, then fused 64x24 GEMM + logits (per 16-lane group) ----
    *(float4*)&hs[gb][q * 4] = make_float4(v0, v1, v2, v3);
    __syncwarp();

    int j0 = q;              // output col q (always < 24 since q < 16)
    int j1 = 16 + q;         // valid when q < 8
    float g0 = 0.f, g1 = 0.f;
#pragma unroll
    for (int k = 0; k < F1; k++) {
        float hv = hs[gb][k];
        g0 += hv * w2s[k * F2 + j0];
        if (q < 8) g1 += hv * w2s[k * F2 + j1];
    }
    xs[gb][j0] = g0;
    g_xw2h[(size_t)n * XW2S + j0] = __float2half_rn(g0);
    if (q < 8) {
        xs[gb][j1] = g1;
        g_xw2h[(size_t)n * XW2S + j1] = __float2half_rn(g1);
    }
    __syncwarp();

    if (q < 8) {
        float ps = xs[gb][q * 3] * __ldg(&a2s[q * 3])
                 + xs[gb][q * 3 + 1] * __ldg(&a2s[q * 3 + 1])
                 + xs[gb][q * 3 + 2] * __ldg(&a2s[q * 3 + 2]);
        float pd = xs[gb][q * 3] * __ldg(&a2d[q * 3])
                 + xs[gb][q * 3 + 1] * __ldg(&a2d[q * 3 + 1])
                 + xs[gb][q * 3 + 2] * __ldg(&a2d[q * 3 + 2]);
        g_al2s[n * H2 + q] = ps;
        g_al2d[n * H2 + q] = pd;
    }
}

// ---------------- agg2: CSR gather (fp16 values), 1 warp/node -------------
__global__ void __launch_bounds__(256) agg2_kernel(const float* __restrict__ b2,
                                                   float* __restrict__ out) {
    int n = (blockIdx.x * 256 + threadIdx.x) >> 5;
    int lane = threadIdx.x & 31;
    int chead = (lane < F2) ? (lane / 3) : 0;

    float ald = 0.f, ex_self = 0.f;
    if (lane < 8) {
        ald = g_al2d[n * H2 + lane];
        ex_self = __expf(leaky(g_al2s[n * H2 + lane] + ald));
    }
    float sex = ex_self;
    float eh = __shfl_sync(0xffffffffu, ex_self, chead, 32);
    float vself = (lane < F2) ? __half2float(g_xw2h[(size_t)n * XW2S + lane]) : 0.f;
    float acc0 = eh * vself;
    float acc1 = 0.f;

    int p = g_rowptr[n];
    int deg = g_rowptr[n + 1] - p;

    int i = 0;
    for (; i + 1 < deg; i += 2) {
        int s0 = __ldg(&g_esrc[p + i]);
        int s1 = __ldg(&g_esrc[p + i + 1]);
        float ex0 = 0.f, ex1 = 0.f;
        if (lane < 8) {
            ex0 = __expf(leaky(g_al2s[s0 * H2 + lane] + ald));
            ex1 = __expf(leaky(g_al2s[s1 * H2 + lane] + ald));
        }
        float v0 = (lane < F2) ? __half2float(g_xw2h[(size_t)s0 * XW2S + lane]) : 0.f;
        float v1 = (lane < F2) ? __half2float(g_xw2h[(size_t)s1 * XW2S + lane]) : 0.f;
        float e0 = __shfl_sync(0xffffffffu, ex0, chead, 32);
        float e1 = __shfl_sync(0xffffffffu, ex1, chead, 32);
        acc0 += e0 * v0;
        acc1 += e1 * v1;
        sex += ex0 + ex1;
    }
    if (i < deg) {
        int s0 = __ldg(&g_esrc[p + i]);
        float ex0 = 0.f;
        if (lane < 8)
            ex0 = __expf(leaky(g_al2s[s0 * H2 + lane] + ald));
        float e0 = __shfl_sync(0xffffffffu, ex0, chead, 32);
        float v0 = (lane < F2) ? __half2float(g_xw2h[(size_t)s0 * XW2S + lane]) : 0.f;
        acc0 += e0 * v0;
        sex += ex0;
    }
    acc0 += acc1;

    float inv = 1.f / (__shfl_sync(0xffffffffu, sex, chead, 32) + 1e-16f);
    float val = acc0 * inv;

    float s = 0.f;
#pragma unroll
    for (int h = 0; h < H2; h++)
        s += __shfl_sync(0xffffffffu, val, h * 3 + (lane & 3), 32);
    float logit = s * 0.125f + ((lane < 3) ? __ldg(&b2[lane]) : 0.f);

    float l0 = __shfl_sync(0xffffffffu, logit, 0, 32);
    float l1 = __shfl_sync(0xffffffffu, logit, 1, 32);
    float l2 = __shfl_sync(0xffffffffu, logit, 2, 32);
    if (lane < 3) {
        float m = fmaxf(l0, fmaxf(l1, l2));
        float e0 = __expf(l0 - m), e1 = __expf(l1 - m), e2 = __expf(l2 - m);
        float invs = 1.f / (e0 + e1 + e2);
        out[n * 3 + lane] = __expf(logit - m) * invs;
    }
}

// ---------------- launch ----------------------------------------------------
extern "C" void kernel_launch(void* const* d_in, const int* in_sizes, int n_in,
                              void* d_out, int out_size) {
    const float* x   = (const float*)d_in[0];
    const float* W1  = (const float*)d_in[1];
    const float* a1s = (const float*)d_in[2];
    const float* a1d = (const float*)d_in[3];
    const float* b1  = (const float*)d_in[4];
    const float* W2  = (const float*)d_in[5];
    const float* a2s = (const float*)d_in[6];
    const float* a2d = (const float*)d_in[7];
    const float* b2  = (const float*)d_in[8];
    const void*  ei  = (const void*)d_in[9];
    float* out = (float*)d_out;

    (void)in_sizes; (void)n_in; (void)out_size;

    static int init_done = 0;
    static cudaStream_t sB;
    static cudaEvent_t evRoot, evB;
    if (!init_done) {
        cudaFuncSetAttribute(gemm1_mma,
                             cudaFuncAttributeMaxDynamicSharedMemorySize,
                             SM_TOTAL);
        cudaStreamCreateWithFlags(&sB, cudaStreamNonBlocking);
        cudaEventCreateWithFlags(&evRoot, cudaEventDisableTiming);
        cudaEventCreateWithFlags(&evB, cudaEventDisableTiming);
        init_done = 1;
    }

    // root
    detect_zcnt_kernel<<<(N_NODES + 255) / 256, 256>>>((const unsigned int*)ei);
    cudaEventRecord(evRoot, 0);
    cudaStreamWaitEvent(sB, evRoot, 0);

    // branch B (CSR build) on secondary stream
    hist_kernel<<<(N_EDGES + 255) / 256, 256, 0, sB>>>(ei);
    blocksum_kernel<<<NB_SCAN, 256, 0, sB>>>();
    scan_bsum_kernel<<<1, 512, 0, sB>>>();
    rowptr_kernel<<<NB_SCAN, 256, 0, sB>>>();
    scatter_kernel<<<(N_EDGES + 255) / 256, 256, 0, sB>>>(ei);
    cudaEventRecord(evB, sB);

    // branch A (dense path) on main stream
    prep_w_kernel<<<(F1 * KPAD + 255) / 256, 256>>>(W1);
    gemm1_mma<<<(N_NODES + 127) / 128, 256, SM_TOTAL>>>(x, a1s, a1d);

    // join, then fused aggregation pipeline
    cudaStreamWaitEvent(0, evB, 0);
    agg1_fused<<<(N_NODES * 16) / 256, 256>>>(b1, W2, a2s, a2d);
    agg2_kernel<<<(N_NODES * 32) / 256, 256>>>(b2, out);
}